// round 1
// baseline (speedup 1.0000x reference)
#include <cuda_runtime.h>

#define BB 4
#define CC 256
#define HH 256
#define WW 256
#define HWSZ (HH * WW)
#define NPIX (BB * HWSZ)

// Per-pixel precomputed maps (channel-independent).
// g_info bits: 0 = gt class (0/1), 1 = correct (pred==gt), 2 = edge
__device__ unsigned char g_info[NPIX];
// g_msecnt: 0 if pixel not mse-masked, else cnt_corr (1..24)
__device__ unsigned char g_msecnt[NPIX];
__device__ double g_loss[2];
__device__ int g_nsel[2];
__device__ int g_cal[2];

// ---------------- Kernel A: per-pixel info (pred, correct, edge) -----------
__global__ void kernA(const int* __restrict__ gt, const float* __restrict__ clf) {
    int p = blockIdx.x * blockDim.x + threadIdx.x;
    if (p == 0) {
        g_loss[0] = 0.0; g_loss[1] = 0.0;
        g_nsel[0] = 0; g_nsel[1] = 0;
        g_cal[0] = 0; g_cal[1] = 0;
    }
    int b = p >> 16;
    int hw = p & (HWSZ - 1);
    int h = hw >> 8;
    int w = hw & (WW - 1);
    int g = gt[p];
    float c0 = clf[(size_t)(b * 2) * HWSZ + hw];
    float c1 = clf[(size_t)(b * 2 + 1) * HWSZ + hw];
    int pred = (c1 > c0) ? 1 : 0;               // argmax ties -> index 0
    int correct = (pred == g) ? 1 : 0;
    int edge = (g == -1) ? 1 : 0;
    if (h < HH - 5) edge |= (gt[p + 5 * WW] != g) ? 1 : 0;
    if (w < WW - 5) edge |= (gt[p + 5] != g) ? 1 : 0;
    g_info[p] = (unsigned char)((g & 1) | (correct << 1) | (edge << 2));
}

// ---------------- Kernel B: ring counts, mse/cal masks, counters -----------
__global__ void kernB() {
    int p = blockIdx.x * blockDim.x + threadIdx.x;
    int hw = p & (HWSZ - 1);
    int h = hw >> 8;
    int w = hw & (WW - 1);
    unsigned info = g_info[p];
    int g = info & 1;
    int correct = (info >> 1) & 1;
    int edge = (info >> 2) & 1;
    int cntCorr = 0, cntCls = 0;
#pragma unroll
    for (int dh = -2; dh <= 2; dh++) {
#pragma unroll
        for (int dw = -2; dw <= 2; dw++) {
            if (dh == 0 && dw == 0) continue;
            int hh = h + dh, wp = w + dw;
            if ((unsigned)hh < HH && (unsigned)wp < WW) {
                unsigned qi = g_info[p + dh * WW + dw];
                int same = ((int)(qi & 1) == g) ? 1 : 0;
                cntCls += same;
                cntCorr += same & (int)((qi >> 1) & 1);
            }
        }
    }
    int mse = correct & edge & (cntCorr >= 1 ? 1 : 0);
    int cal = edge & (cntCls >= 1 ? 1 : 0);
    g_msecnt[p] = (unsigned char)(mse ? cntCorr : 0);

    unsigned bm;
    bm = __ballot_sync(0xFFFFFFFFu, mse && g == 0);
    if ((threadIdx.x & 31) == 0 && bm) atomicAdd(&g_nsel[0], __popc(bm));
    bm = __ballot_sync(0xFFFFFFFFu, mse && g == 1);
    if ((threadIdx.x & 31) == 0 && bm) atomicAdd(&g_nsel[1], __popc(bm));
    bm = __ballot_sync(0xFFFFFFFFu, cal && g == 0);
    if ((threadIdx.x & 31) == 0 && bm) atomicAdd(&g_cal[0], __popc(bm));
    bm = __ballot_sync(0xFFFFFFFFu, cal && g == 1);
    if ((threadIdx.x & 31) == 0 && bm) atomicAdd(&g_cal[1], __popc(bm));
}

// ---------------- Kernel C: main loss (separable 2-class box filter) -------
// Block (32,8). Lanes = 32 consecutive w (columns w0-2..w0+29), 28 output cols.
// Each thread owns 4 column-sum rows (8 x-rows in registers, vertical pass in
// registers via prefix sums). Horizontal pass: 5 smem reads of the
// class-selected column sums, only at mse-masked pixels. Channel loop inside
// block; per-pixel flags/masks loaded once into registers.
#define TWOUT 28
#define THR 32
#define NCHUNK 4
#define CHPER (CC / NCHUNK)

__global__ void __launch_bounds__(256, 2) kernC(const float* __restrict__ x) {
    __shared__ float csum[2][2][THR][33];  // [buf][class][row][lane]
    __shared__ float red0[256], red1[256];

    int tx = threadIdx.x, ty = threadIdx.y;
    int bz = blockIdx.z;
    int b = bz >> 2;
    int chunk = bz & 3;
    int h0 = blockIdx.y * THR;
    int w0 = blockIdx.x * TWOUT;
    int w = w0 - 2 + tx;
    bool colOK = (unsigned)w < WW;
    int cr0 = ty * 4;

    const unsigned char* infoB = g_info + (size_t)b * HWSZ;
    const unsigned char* mseB = g_msecnt + (size_t)b * HWSZ;

    float fc0[8], fc1[8];
    bool rv[8];
    int offs[8];
#pragma unroll
    for (int i = 0; i < 8; i++) {
        int hr = h0 + cr0 - 2 + i;
        bool v = colOK && ((unsigned)hr < HH);
        rv[i] = v;
        int off = hr * WW + w;
        offs[i] = off;
        unsigned qi = v ? (unsigned)infoB[off] : 0u;
        int gq = qi & 1, cq = (qi >> 1) & 1;
        fc1[i] = (cq & gq) ? 1.0f : 0.0f;
        fc0[i] = (cq & (gq ^ 1)) ? 1.0f : 0.0f;
    }

    bool outOK = colOK && (tx >= 2) && (tx < 30);
    float inv[4];
    int cls[4];
    bool msk[4];
#pragma unroll
    for (int i = 0; i < 4; i++) {
        int hc = h0 + cr0 + i;
        int off = hc * WW + w;
        unsigned char mc = outOK ? mseB[off] : (unsigned char)0;
        msk[i] = (mc > 0);
        inv[i] = 1.0f / ((float)mc + 1e-5f);
        cls[i] = outOK ? (int)(infoB[off] & 1) : 0;
    }

    float acc0 = 0.f, acc1 = 0.f;
    const float* xb = x + ((size_t)b * CC + (size_t)chunk * CHPER) * HWSZ;

#pragma unroll 2
    for (int ch = 0; ch < CHPER; ch++) {
        const float* xc = xb + (size_t)ch * HWSZ;
        float xi[8];
#pragma unroll
        for (int i = 0; i < 8; i++)
            xi[i] = rv[i] ? __ldg(xc + offs[i]) : 0.0f;

        // vertical prefix sums per class (registers only)
        float P0[8], P1[8];
        float pv0 = 0.f, pv1 = 0.f;
#pragma unroll
        for (int i = 0; i < 8; i++) {
            pv0 = fmaf(xi[i], fc0[i], pv0);
            pv1 = fmaf(xi[i], fc1[i], pv1);
            P0[i] = pv0;
            P1[i] = pv1;
        }
        int buf = ch & 1;
#pragma unroll
        for (int i = 0; i < 4; i++) {
            float cs0 = P0[i + 4] - (i ? P0[i - 1] : 0.f);
            float cs1 = P1[i + 4] - (i ? P1[i - 1] : 0.f);
            csum[buf][0][cr0 + i][tx] = cs0;
            csum[buf][1][cr0 + i][tx] = cs1;
        }
        __syncthreads();  // single barrier per channel (double-buffered csum)
#pragma unroll
        for (int i = 0; i < 4; i++) {
            if (msk[i]) {
                const float* row = &csum[buf][cls[i]][cr0 + i][0];
                float rs = row[tx - 2] + row[tx - 1] + row[tx] + row[tx + 1] + row[tx + 2];
                float xp = xi[i + 2];               // center x (in registers)
                float d = xp - (rs - xp) * inv[i];  // ring = box - center
                float dd = d * d;
                if (cls[i]) acc1 += dd; else acc0 += dd;
            }
        }
    }

    // block reduction -> 2 double atomics per block
    int tid = ty * 32 + tx;
    red0[tid] = acc0;
    red1[tid] = acc1;
    __syncthreads();
    for (int s = 128; s > 0; s >>= 1) {
        if (tid < s) { red0[tid] += red0[tid + s]; red1[tid] += red1[tid + s]; }
        __syncthreads();
    }
    if (tid == 0) {
        atomicAdd(&g_loss[0], (double)red0[0]);
        atomicAdd(&g_loss[1], (double)red1[0]);
    }
}

// ---------------- Kernel D: finalize ---------------------------------------
__global__ void kernD(float* out) {
    double total = 0.0;
    int ncls = 0;
#pragma unroll
    for (int c = 0; c < 2; c++) {
        bool valid = (g_cal[c] >= 1) && (g_nsel[c] >= 1);
        double denom = (double)g_nsel[c] * 256.0;
        if (denom < 1.0) denom = 1.0;
        double lc = g_loss[c] / denom;
        if (valid) { total += lc; ncls++; }
    }
    out[0] = (ncls == 0) ? 0.0f : (float)(total / (double)ncls);
}

extern "C" void kernel_launch(void* const* d_in, const int* in_sizes, int n_in,
                              void* d_out, int out_size) {
    const float* xfeat = (const float*)d_in[0];   // [4,256,256,256] f32
    const float* clf   = (const float*)d_in[1];   // [4,2,256,256]   f32
    const int*   gt    = (const int*)d_in[2];     // [4,256,256]     i32
    float* out = (float*)d_out;

    kernA<<<NPIX / 256, 256>>>(gt, clf);
    kernB<<<NPIX / 256, 256>>>();
    dim3 blk(32, 8);
    dim3 grd((WW + TWOUT - 1) / TWOUT, HH / THR, BB * NCHUNK);  // 10 x 8 x 16
    kernC<<<grd, blk>>>(xfeat);
    kernD<<<1, 1>>>(out);
}